// round 15
// baseline (speedup 1.0000x reference)
#include <cuda_runtime.h>
#include <cuda_bf16.h>

#define NB 16
#define NC 64
#define NH 128
#define NW 128
#define NE 8
#define NGH 16

__device__ float g_pooled[NB * NC];
__device__ float g_probs[NB][NE];
__device__ float g_bcomb[NB][NC];
// A in mma-fragment order: [b][tap][mtile(4)][kc(4)][lane(32)][j(4)] bf16x2 words
#define FRAG_WORDS (NB * 9 * 4 * 4 * 32 * 4)
__device__ unsigned g_wfrag_h[FRAG_WORDS];
__device__ unsigned g_wfrag_l[FRAG_WORDS];

__device__ __forceinline__ unsigned smem_u32(const void* p) {
    return (unsigned)__cvta_generic_to_shared(p);
}

#define LDSM_X4(r0, r1, r2, r3, addr) \
    asm volatile("ldmatrix.sync.aligned.m8n8.x4.shared.b16 {%0,%1,%2,%3}, [%4];" \
                 : "=r"(r0), "=r"(r1), "=r"(r2), "=r"(r3) : "r"(addr))

#define MMA_BF16(d, a0, a1, a2, a3, b0, b1) \
    asm volatile("mma.sync.aligned.m16n8k16.row.col.f32.bf16.bf16.f32 " \
                 "{%0,%1,%2,%3}, {%4,%5,%6,%7}, {%8,%9}, {%0,%1,%2,%3};" \
                 : "+f"(d[0]), "+f"(d[1]), "+f"(d[2]), "+f"(d[3]) \
                 : "r"(a0), "r"(a1), "r"(a2), "r"(a3), "r"(b0), "r"(b1))

// ---------------------------------------------------------------------------
// Kernel 1a: parallel GAP. One block per (b, c).
// ---------------------------------------------------------------------------
__global__ __launch_bounds__(256)
void pool_kernel(const float* __restrict__ x) {
    const int bc = blockIdx.x;
    const int tid = threadIdx.x;
    const float4* p4 = (const float4*)(x + (size_t)bc * NH * NW);

    float s = 0.f;
    #pragma unroll 4
    for (int i = tid; i < (NH * NW) / 4; i += 256) {
        float4 v = p4[i];
        s += (v.x + v.y) + (v.z + v.w);
    }
    #pragma unroll
    for (int o = 16; o > 0; o >>= 1) s += __shfl_xor_sync(0xffffffffu, s, o);

    __shared__ float ws[8];
    if ((tid & 31) == 0) ws[tid >> 5] = s;
    __syncthreads();
    if (tid == 0) {
        float t = 0.f;
        #pragma unroll
        for (int w = 0; w < 8; w++) t += ws[w];
        g_pooled[bc] = t * (1.0f / (NH * NW));
    }
}

// ---------------------------------------------------------------------------
// Kernel 1b: gating MLP + softmax + top-2.
// ---------------------------------------------------------------------------
__global__ void gate_kernel(const float* __restrict__ wg1,
                            const float* __restrict__ bg1,
                            const float* __restrict__ wg2,
                            const float* __restrict__ bg2) {
    const int b = blockIdx.x;
    const int tid = threadIdx.x;  // 64 threads

    __shared__ float pooled[NC];
    __shared__ float hbuf[NGH];
    __shared__ float logits[NE];

    if (tid < NC) pooled[tid] = g_pooled[b * NC + tid];
    __syncthreads();

    if (tid < NGH) {
        float a = bg1[tid];
        #pragma unroll
        for (int c = 0; c < NC; c++) a += pooled[c] * wg1[c * NGH + tid];
        hbuf[tid] = a > 0.f ? a : 0.f;
    }
    __syncthreads();

    if (tid < NE) {
        float a = bg2[tid];
        #pragma unroll
        for (int g = 0; g < NGH; g++) a += hbuf[g] * wg2[g * NE + tid];
        logits[tid] = a;
    }
    __syncthreads();

    if (tid == 0) {
        float m = -1e30f;
        #pragma unroll
        for (int e = 0; e < NE; e++) m = fmaxf(m, logits[e]);
        float p[NE], s = 0.f;
        #pragma unroll
        for (int e = 0; e < NE; e++) { p[e] = expf(logits[e] - m); s += p[e]; }
        float inv = 1.0f / s;
        #pragma unroll
        for (int e = 0; e < NE; e++) p[e] *= inv;
        int i1 = 0;
        #pragma unroll
        for (int e = 1; e < NE; e++) if (p[e] > p[i1]) i1 = e;
        int i2 = -1;
        #pragma unroll
        for (int e = 0; e < NE; e++) {
            if (e == i1) continue;
            if (i2 < 0 || p[e] > p[i2]) i2 = e;
        }
        float denom = p[i1] + p[i2] + 1e-8f;
        #pragma unroll
        for (int e = 0; e < NE; e++)
            g_probs[b][e] = (e == i1 || e == i2) ? p[e] / denom : 0.f;
    }
}

// ---------------------------------------------------------------------------
// Kernel 2: fold routing probs into per-batch weights, split bf16 hi/lo,
// written directly in mma A-fragment order (see R12 derivation).
// ---------------------------------------------------------------------------
__global__ void combine_kernel(const float* __restrict__ w_exp,
                               const float* __restrict__ b_exp) {
    const int idx = blockIdx.x * blockDim.x + threadIdx.x;
    const int total = NB * 9 * NC * NC;
    if (idx < total) {
        const int b   = idx / (9 * NC * NC);
        const int r0  = idx - b * (9 * NC * NC);
        const int tap = r0 / (NC * NC);
        const int r1  = r0 - tap * (NC * NC);
        const int co  = r1 / NC;
        const int ci  = r1 - co * NC;
        float s = 0.f;
        #pragma unroll
        for (int e = 0; e < NE; e++)
            s += g_probs[b][e] * w_exp[((size_t)(e * NC + co) * NC + ci) * 9 + tap];
        const __nv_bfloat16 hi = __float2bfloat16(s);
        const __nv_bfloat16 lo = __float2bfloat16(s - __bfloat162float(hi));

        const int mt = co >> 4, r = co & 15;
        const int kc = ci >> 4, c = ci & 15;
        const int lane = ((r & 7) << 2) | ((c & 7) >> 1);
        const int j    = ((c >> 3) << 1) | (r >> 3);
        const int word = ((((b * 9 + tap) * 4 + mt) * 4 + kc) * 32 + lane) * 4 + j;
        ((__nv_bfloat16*)g_wfrag_h)[word * 2 + (c & 1)] = hi;
        ((__nv_bfloat16*)g_wfrag_l)[word * 2 + (c & 1)] = lo;
    }
    if (idx < NB * NC) {
        const int b = idx / NC, c = idx - b * NC;
        float s = 0.f;
        #pragma unroll
        for (int e = 0; e < NE; e++) s += g_probs[b][e] * b_exp[e * NC + c];
        g_bcomb[b][c] = s;
    }
}

// ---------------------------------------------------------------------------
// Kernel 3: implicit-GEMM conv. ALL A taps staged in smem once (fragment
// order, read back with plain LDS.128); B staged once (hi/lo, swizzled, for
// ldmatrix). ONE barrier total; tap loop is barrier-free.
// CTA: 16(h) x 8(w) pixels of one batch, 1 CTA/SM (193.5 KB smem).
// 8 warps, each m32 x n32: mw2 = warp&1 (co 32-half), nw4 = warp>>1
// (pixel-row quad). 3-pass split bf16.
// ---------------------------------------------------------------------------
#define TPY 16
#define TPX 8
#define PRW (TPX + 2)                     // 10
#define PROWS ((TPY + 2) * PRW)           // 180
#define B_BYTES (PROWS * NC * 2 * 2)      // 46080
#define A_U4_PER_B (9 * 4 * 4 * 32)       // 4608 uint4 per split per batch
#define A_BYTES (A_U4_PER_B * 16)         // 73728 per split
#define SMEM_BYTES (B_BYTES + 2 * A_BYTES)  // 193536

__global__ __launch_bounds__(256)
void conv_mma_kernel(const float* __restrict__ x, float* __restrict__ out) {
    const int b  = blockIdx.z;
    const int X0 = blockIdx.x * TPX;
    const int Y0 = blockIdx.y * TPY;

    extern __shared__ __align__(16) char smem_raw[];
    __nv_bfloat16* Bh = (__nv_bfloat16*)smem_raw;        // [180][64] swizzled
    __nv_bfloat16* Bl = Bh + PROWS * NC;
    uint4* AhS = (uint4*)(smem_raw + B_BYTES);           // fragment order
    uint4* AlS = AhS + A_U4_PER_B;

    const int tid  = threadIdx.x;
    const int lane = tid & 31;
    const int warp = tid >> 5;
    const int mw2  = warp & 1;    // co 32-half
    const int nw4  = warp >> 1;   // pixel-row quad (rows nw4*4 .. +3)

    // ---- stage input tile B (hi/lo split, swizzled) ----
    const float* xb = x + (size_t)b * NC * NH * NW;
    for (int i = tid; i < PROWS * NC; i += 256) {
        const int ci = i / PROWS;
        const int r  = i - ci * PROWS;
        const int ly = r / PRW, lx = r - ly * PRW;
        const int gy = Y0 - 1 + ly, gx = X0 - 1 + lx;
        float v = 0.f;
        if (gy >= 0 && gy < NH && gx >= 0 && gx < NW)
            v = xb[ci * (NH * NW) + gy * NW + gx];
        const __nv_bfloat16 hi = __float2bfloat16(v);
        const __nv_bfloat16 lo = __float2bfloat16(v - __bfloat162float(hi));
        const int off = r * NC + ((((ci >> 3) ^ (r & 7)) << 3) | (ci & 7));
        Bh[off] = hi;
        Bl[off] = lo;
    }
    // ---- stage ALL A fragments for this batch (linear copy) ----
    {
        const uint4* gh = (const uint4*)g_wfrag_h + (size_t)b * A_U4_PER_B;
        const uint4* gl = (const uint4*)g_wfrag_l + (size_t)b * A_U4_PER_B;
        for (int i = tid; i < A_U4_PER_B; i += 256) {
            AhS[i] = gh[i];
            AlS[i] = gl[i];
        }
    }
    __syncthreads();   // the only barrier

    const unsigned BhB = smem_u32(Bh), BlB = smem_u32(Bl);

    // B ldmatrix x4 lane roles: bf = lane>>4 (row within pair),
    // bkh = (lane>>3)&1 (k-half), bjx = lane&7 (pixel x)
    const int bf  = lane >> 4;
    const int bkh = (lane >> 3) & 1;
    const int bjx = lane & 7;

    float acc[2][4][4];   // [m (co16 within half)][p (row in quad)][quad]
    #pragma unroll
    for (int m = 0; m < 2; m++)
        #pragma unroll
        for (int p = 0; p < 4; p++)
            #pragma unroll
            for (int q = 0; q < 4; q++) acc[m][p][q] = 0.f;

    #pragma unroll 1
    for (int tap = 0; tap < 9; tap++) {
        const int ky = tap / 3, kx = tap - ky * 3;
        // B rows for this warp's 4 pixel-rows (nf = nw4*4 + 2*pair + bf)
        const int row0 = (nw4 * 4 + bf + ky) * PRW + bjx + kx;      // pair 0
        const int row1 = row0 + 2 * PRW;                            // pair 1
        const int sw0 = row0 & 7, sw1 = row1 & 7;
        // A smem uint4 index base: ((tap*4 + mt)*4 + kc)*32 + lane
        const int amt0 = (tap * 4 + mw2 * 2) * 4;       // m=0
        const int amt1 = (tap * 4 + mw2 * 2 + 1) * 4;   // m=1

        #pragma unroll
        for (int kc = 0; kc < 4; kc++) {
            const int g = (kc << 1) | bkh;
            const unsigned bu0 = (unsigned)((row0 << 7) + ((g ^ sw0) << 4));
            const unsigned bu1 = (unsigned)((row1 << 7) + ((g ^ sw1) << 4));
            unsigned bh[8], bl[8];
            LDSM_X4(bh[0], bh[1], bh[2], bh[3], BhB + bu0);
            LDSM_X4(bh[4], bh[5], bh[6], bh[7], BhB + bu1);
            LDSM_X4(bl[0], bl[1], bl[2], bl[3], BlB + bu0);
            LDSM_X4(bl[4], bl[5], bl[6], bl[7], BlB + bu1);

            const uint4 ah0 = AhS[(amt0 + kc) * 32 + lane];
            const uint4 ah1 = AhS[(amt1 + kc) * 32 + lane];
            const uint4 al0 = AlS[(amt0 + kc) * 32 + lane];
            const uint4 al1 = AlS[(amt1 + kc) * 32 + lane];

            #pragma unroll
            for (int p = 0; p < 4; p++) {
                const unsigned b0 = bh[2 * p], b1 = bh[2 * p + 1];
                const unsigned c0 = bl[2 * p], c1 = bl[2 * p + 1];
                MMA_BF16(acc[0][p], ah0.x, ah0.y, ah0.z, ah0.w, b0, b1);
                MMA_BF16(acc[1][p], ah1.x, ah1.y, ah1.z, ah1.w, b0, b1);
                MMA_BF16(acc[0][p], ah0.x, ah0.y, ah0.z, ah0.w, c0, c1);
                MMA_BF16(acc[1][p], ah1.x, ah1.y, ah1.z, ah1.w, c0, c1);
                MMA_BF16(acc[0][p], al0.x, al0.y, al0.z, al0.w, b0, b1);
                MMA_BF16(acc[1][p], al1.x, al1.y, al1.z, al1.w, b0, b1);
            }
        }
    }

    // ---- epilogue: bias + residual ----
    // acc[m][p][q]: co = mw2*32 + m*16 + (lane>>2) + (q>>1)*8
    //               pixel row y = nw4*4 + p, x = (lane&3)*2 + (q&1)
    #pragma unroll
    for (int m = 0; m < 2; m++) {
        #pragma unroll
        for (int p = 0; p < 4; p++) {
            const int gy = Y0 + nw4 * 4 + p;
            const int gx = X0 + ((lane & 3) << 1);
            #pragma unroll
            for (int h = 0; h < 2; h++) {
                const int co = mw2 * 32 + m * 16 + (lane >> 2) + h * 8;
                const float bias = g_bcomb[b][co];
                const size_t o = ((size_t)(b * NC + co) * NH + gy) * NW + gx;
                const float2 res = *(const float2*)(x + o);
                float2 v;
                v.x = acc[m][p][h * 2 + 0] + bias + res.x;
                v.y = acc[m][p][h * 2 + 1] + bias + res.y;
                *(float2*)(out + o) = v;
            }
        }
    }
}

extern "C" void kernel_launch(void* const* d_in, const int* in_sizes, int n_in,
                              void* d_out, int out_size) {
    const float* x     = (const float*)d_in[0];
    const float* wg1   = (const float*)d_in[1];
    const float* bg1   = (const float*)d_in[2];
    const float* wg2   = (const float*)d_in[3];
    const float* bg2   = (const float*)d_in[4];
    const float* w_exp = (const float*)d_in[5];
    const float* b_exp = (const float*)d_in[6];
    float* out = (float*)d_out;

    pool_kernel<<<NB * NC, 256>>>(x);
    gate_kernel<<<NB, 64>>>(wg1, bg1, wg2, bg2);

    const int total = NB * 9 * NC * NC;
    combine_kernel<<<(total + 255) / 256, 256>>>(w_exp, b_exp);

    static bool attr_set = false;
    if (!attr_set) {
        cudaFuncSetAttribute(conv_mma_kernel,
                             cudaFuncAttributeMaxDynamicSharedMemorySize,
                             SMEM_BYTES);
        attr_set = true;
    }
    dim3 grid(NW / TPX, NH / TPY, NB);   // (16, 8, 16)
    conv_mma_kernel<<<grid, 256, SMEM_BYTES>>>(x, out);
}